// round 15
// baseline (speedup 1.0000x reference)
#include <cuda_runtime.h>
#include <cstdint>
#include <math.h>

#define Bv 2
#define Tv 1024
#define Cv 1024
#define Hv 16
#define Dv 64
#define BHv 32
#define NCH 16          // 16 chunks of 64 tokens
#define QSZ (BHv*Tv*Dv) // 2,097,152

// ---------------- scratch (no allocations allowed) ----------------
__device__ float g_qkv[3u*BHv*Tv*Dv];      // [3][BH][T][D]
__device__ float g_ysharp[BHv*Tv*Dv];      // [BH][T][D]
__device__ float g_yintra[BHv*Tv*Dv];      // [BH][T][D]
__device__ float g_dintra[BHv*Tv];         // [BH][T]
__device__ float g_Sc[BHv*NCH*Dv*Dv];      // chunk states -> exclusive prefix (in place)
__device__ float g_ks[BHv*NCH*Dv];         // chunk ksum   -> exclusive prefix (in place)
__device__ float g_y[Bv*Tv*Cv];            // combined attention output [B,T,C]

__device__ __forceinline__ float elu1(float x) {        // elu(x)+1
    return x > 0.f ? x + 1.f : __expf(x);
}

// ---------------- mma / cp.async helpers ----------------
__device__ __forceinline__ void cpa16(uint32_t s, const void* g) {
    asm volatile("cp.async.cg.shared.global [%0], [%1], 16;\n" :: "r"(s), "l"(g));
}
__device__ __forceinline__ void cpa_commit() {
    asm volatile("cp.async.commit_group;\n");
}
template <int N>
__device__ __forceinline__ void cpa_wait() {
    asm volatile("cp.async.wait_group %0;\n" :: "n"(N));
}
__device__ __forceinline__ void mma_tf32(float* c, const float* a, const float* b) {
    asm volatile(
        "mma.sync.aligned.m16n8k8.row.col.f32.tf32.tf32.f32 "
        "{%0,%1,%2,%3}, {%4,%5,%6,%7}, {%8,%9}, {%0,%1,%2,%3};\n"
        : "+f"(c[0]), "+f"(c[1]), "+f"(c[2]), "+f"(c[3])
        : "r"(__float_as_uint(a[0])), "r"(__float_as_uint(a[1])),
          "r"(__float_as_uint(a[2])), "r"(__float_as_uint(a[3])),
          "r"(__float_as_uint(b[0])), "r"(__float_as_uint(b[1])));
}
__device__ __forceinline__ float tf32_rna(float x) {
    float r;
    asm("cvt.rna.tf32.f32 %0, %1;\n" : "=f"(r) : "f"(x));
    return r;
}

// =================== K1: QKV GEMM (TF32 tensor cores) ===================
#define GSTR 20
__global__ void __launch_bounds__(256, 2) qkv_gemm_kernel(const float* __restrict__ X,
                                                          const float* __restrict__ W,
                                                          const float* __restrict__ bias) {
    __shared__ float As[2][128][GSTR];
    __shared__ float Bs[2][128][GSTR];

    int tid = threadIdx.x;
    int lane = tid & 31, wid = tid >> 5;
    int wm = (wid >> 2) * 64;
    int wn = (wid & 3) * 32;
    int bm = blockIdx.y * 128, bn = blockIdx.x * 128;

    const float* Xb = X + (size_t)bm * 1024;
    const float* Wb = W + (size_t)bn * 1024;

    int lrow = tid >> 2;
    int lc4  = (tid & 3) * 4;

    float c[4][4][4];
#pragma unroll
    for (int mt = 0; mt < 4; mt++)
#pragma unroll
        for (int nt = 0; nt < 4; nt++)
#pragma unroll
            for (int r = 0; r < 4; r++) c[mt][nt][r] = 0.f;

    auto issue = [&](int st, int k0) {
#pragma unroll
        for (int i = 0; i < 2; i++) {
            int row = lrow + i * 64;
            uint32_t sa = (uint32_t)__cvta_generic_to_shared(&As[st][row][lc4]);
            cpa16(sa, &Xb[(size_t)row * 1024 + k0 + lc4]);
            uint32_t sb = (uint32_t)__cvta_generic_to_shared(&Bs[st][row][lc4]);
            cpa16(sb, &Wb[(size_t)row * 1024 + k0 + lc4]);
        }
    };

    const int NK = 64;
    issue(0, 0);
    cpa_commit();

    int lr4 = lane >> 2;
    int lk  = lane & 3;

    for (int kt = 0; kt < NK; kt++) {
        int s = kt & 1;
        if (kt + 1 < NK) { issue(s ^ 1, (kt + 1) * 16); cpa_commit(); cpa_wait<1>(); }
        else             { cpa_wait<0>(); }
        __syncthreads();

#pragma unroll
        for (int ks = 0; ks < 2; ks++) {
            int k8 = ks * 8;
            float a[4][4], b[4][2];
#pragma unroll
            for (int mt = 0; mt < 4; mt++) {
                int r = wm + mt * 16 + lr4;
                a[mt][0] = As[s][r][k8 + lk];
                a[mt][1] = As[s][r + 8][k8 + lk];
                a[mt][2] = As[s][r][k8 + lk + 4];
                a[mt][3] = As[s][r + 8][k8 + lk + 4];
            }
#pragma unroll
            for (int nt = 0; nt < 4; nt++) {
                int n = wn + nt * 8 + lr4;
                b[nt][0] = Bs[s][n][k8 + lk];
                b[nt][1] = Bs[s][n][k8 + lk + 4];
            }
#pragma unroll
            for (int mt = 0; mt < 4; mt++)
#pragma unroll
                for (int nt = 0; nt < 4; nt++)
                    mma_tf32(c[mt][nt], a[mt], b[nt]);
        }
        __syncthreads();
    }

#pragma unroll
    for (int nt = 0; nt < 4; nt++) {
        int n0 = bn + wn + nt * 8 + lk * 2;
#pragma unroll
        for (int jj = 0; jj < 2; jj++) {
            int n = n0 + jj;
            float bb = __ldg(&bias[n]);
            int part = n >> 10, rem = n & 1023, h = rem >> 6, d = rem & 63;
            size_t cbase = (size_t)part * QSZ + (size_t)h * Tv * Dv + d;
#pragma unroll
            for (int mt = 0; mt < 4; mt++) {
                int m0 = bm + wm + mt * 16 + lr4;
#pragma unroll
                for (int ii = 0; ii < 2; ii++) {
                    int m = m0 + ii * 8;
                    int bi = m >> 10, t = m & 1023;
                    g_qkv[cbase + ((size_t)bi * Hv * Tv + t) * Dv] =
                        c[mt][nt][ii * 2 + jj] + bb;
                }
            }
        }
    }
}

// =================== K2: flash softmax attention (causal, TF32 mma) ===================
// grid (8, BH): block pi handles q-tiles (pi, 15-pi) -> 17 k-tiles each.
// 128 threads = 4 warps. K pre-split hi/lo; V row-major (stride 72, conflict-free).
// K/V of the NEXT tile are prefetched into registers during current tile's mma.
#define FSTR 68
#define VSTR 72
__global__ void __launch_bounds__(128, 2) flash_kernel() {
    extern __shared__ float sm[];
    float* Qhi = sm;                 // [64][FSTR]
    float* Qlo = Qhi + 64 * FSTR;    // [64][FSTR]
    float* Khi = Qlo + 64 * FSTR;    // [64][FSTR]
    float* Klo = Khi + 64 * FSTR;    // [64][FSTR]
    float* Ps  = Klo + 64 * FSTR;    // [64][FSTR]
    float* Vs  = Ps  + 64 * FSTR;    // [64][VSTR] row-major V

    int bh = blockIdx.y;
    int pi = blockIdx.x;
    int tid = threadIdx.x, lane = tid & 31, wid = tid >> 5;
    int gr = lane >> 2, gc = lane & 3;
    int m0 = wid * 16;

    float4 kr[8], vr[8];   // prefetch registers for one 64x64 K tile + V tile

    auto ldg_tile = [&](int kt) {
        const float* kb = g_qkv + QSZ + ((size_t)bh * Tv + kt * 64) * Dv;
        const float* vb = kb + QSZ;
#pragma unroll
        for (int j = 0; j < 8; j++) {
            int i = tid + j * 128;
            int row = i >> 4, c4 = (i & 15) * 4;
            kr[j] = *(const float4*)&kb[row * 64 + c4];
            vr[j] = *(const float4*)&vb[row * 64 + c4];
        }
    };
    auto sts_tile = [&]() {
#pragma unroll
        for (int j = 0; j < 8; j++) {
            int i = tid + j * 128;
            int row = i >> 4, c4 = (i & 15) * 4;
            float4 f = kr[j];
            float h0 = tf32_rna(f.x), h1 = tf32_rna(f.y);
            float h2 = tf32_rna(f.z), h3 = tf32_rna(f.w);
            float* dh = &Khi[row * FSTR + c4];
            dh[0] = h0; dh[1] = h1; dh[2] = h2; dh[3] = h3;
            float* dl = &Klo[row * FSTR + c4];
            dl[0] = f.x - h0; dl[1] = f.y - h1;
            dl[2] = f.z - h2; dl[3] = f.w - h3;
            *(float4*)&Vs[row * VSTR + c4] = vr[j];
        }
    };

#pragma unroll 1
    for (int pass = 0; pass < 2; pass++) {
        int qt = pass == 0 ? pi : 15 - pi;
        int q0 = qt * 64;

        ldg_tile(0);   // prefetch first K/V tile of this pass

        __syncthreads();   // all warps done with previous pass's smem
        const float* qb = g_qkv + ((size_t)bh * Tv + q0) * Dv;
        for (int i = tid; i < 1024; i += 128) {
            int row = i >> 4, c4 = (i & 15) * 4;
            float4 f = *(const float4*)&qb[row * 64 + c4];
            float q0v = f.x * 0.125f, q1v = f.y * 0.125f;
            float q2v = f.z * 0.125f, q3v = f.w * 0.125f;
            float h0 = tf32_rna(q0v), h1 = tf32_rna(q1v);
            float h2 = tf32_rna(q2v), h3 = tf32_rna(q3v);
            float* dh = &Qhi[row * FSTR + c4];
            dh[0] = h0; dh[1] = h1; dh[2] = h2; dh[3] = h3;
            float* dl = &Qlo[row * FSTR + c4];
            dl[0] = q0v - h0; dl[1] = q1v - h1;
            dl[2] = q2v - h2; dl[3] = q3v - h3;
        }

        float m_i[2] = {-1e30f, -1e30f};
        float l_i[2] = {0.f, 0.f};
        float o[8][4];
#pragma unroll
        for (int dt = 0; dt < 8; dt++)
#pragma unroll
            for (int r = 0; r < 4; r++) o[dt][r] = 0.f;

#pragma unroll 1
        for (int kt = 0; kt <= qt; kt++) {
            __syncthreads();            // K/V buffers free (prev tile consumed)
            sts_tile();                 // store prefetched tile kt
            if (kt < qt) ldg_tile(kt + 1);   // prefetch next; overlaps mma below
            __syncthreads();            // tile kt ready

            // ---- S = Q K^T (3-term split-tf32; both sides pre-split) ----
            float s[8][4];
#pragma unroll
            for (int nt = 0; nt < 8; nt++)
#pragma unroll
                for (int r = 0; r < 4; r++) s[nt][r] = 0.f;

#pragma unroll
            for (int ks = 0; ks < 8; ks++) {
                int k = ks * 8;
                float ah[4], al[4];
                ah[0] = Qhi[(m0 + gr) * FSTR + k + gc];
                ah[1] = Qhi[(m0 + gr + 8) * FSTR + k + gc];
                ah[2] = Qhi[(m0 + gr) * FSTR + k + gc + 4];
                ah[3] = Qhi[(m0 + gr + 8) * FSTR + k + gc + 4];
                al[0] = Qlo[(m0 + gr) * FSTR + k + gc];
                al[1] = Qlo[(m0 + gr + 8) * FSTR + k + gc];
                al[2] = Qlo[(m0 + gr) * FSTR + k + gc + 4];
                al[3] = Qlo[(m0 + gr + 8) * FSTR + k + gc + 4];
#pragma unroll
                for (int nt = 0; nt < 8; nt++) {
                    float bhv[2], blv[2];
                    bhv[0] = Khi[(nt * 8 + gr) * FSTR + k + gc];
                    bhv[1] = Khi[(nt * 8 + gr) * FSTR + k + gc + 4];
                    blv[0] = Klo[(nt * 8 + gr) * FSTR + k + gc];
                    blv[1] = Klo[(nt * 8 + gr) * FSTR + k + gc + 4];
                    mma_tf32(s[nt], ah, bhv);
                    mma_tf32(s[nt], ah, blv);
                    mma_tf32(s[nt], al, bhv);
                }
            }

            // ---- causal mask (only the diagonal tile is partial) ----
            if (kt == qt) {
                int lr = m0 + gr;
#pragma unroll
                for (int nt = 0; nt < 8; nt++) {
                    int c0 = nt * 8 + 2 * gc;
                    if (c0 > lr)     s[nt][0] = -1e30f;
                    if (c0 + 1 > lr) s[nt][1] = -1e30f;
                    if (c0 > lr + 8)     s[nt][2] = -1e30f;
                    if (c0 + 1 > lr + 8) s[nt][3] = -1e30f;
                }
            }

            // ---- online softmax ----
            float mx[2] = {m_i[0], m_i[1]};
#pragma unroll
            for (int nt = 0; nt < 8; nt++) {
                mx[0] = fmaxf(mx[0], fmaxf(s[nt][0], s[nt][1]));
                mx[1] = fmaxf(mx[1], fmaxf(s[nt][2], s[nt][3]));
            }
#pragma unroll
            for (int off = 1; off <= 2; off <<= 1) {
                mx[0] = fmaxf(mx[0], __shfl_xor_sync(0xffffffffu, mx[0], off));
                mx[1] = fmaxf(mx[1], __shfl_xor_sync(0xffffffffu, mx[1], off));
            }
            float corr0 = __expf(m_i[0] - mx[0]);
            float corr1 = __expf(m_i[1] - mx[1]);
            m_i[0] = mx[0]; m_i[1] = mx[1];

            float psum[2] = {0.f, 0.f};
#pragma unroll
            for (int nt = 0; nt < 8; nt++) {
                float p0 = tf32_rna(__expf(s[nt][0] - mx[0]));
                float p1 = tf32_rna(__expf(s[nt][1] - mx[0]));
                float p2 = tf32_rna(__expf(s[nt][2] - mx[1]));
                float p3 = tf32_rna(__expf(s[nt][3] - mx[1]));
                psum[0] += p0 + p1; psum[1] += p2 + p3;
                int cb = nt * 8 + 2 * gc;
                Ps[(m0 + gr) * FSTR + cb]     = p0;
                Ps[(m0 + gr) * FSTR + cb + 1] = p1;
                Ps[(m0 + gr + 8) * FSTR + cb]     = p2;
                Ps[(m0 + gr + 8) * FSTR + cb + 1] = p3;
            }
#pragma unroll
            for (int off = 1; off <= 2; off <<= 1) {
                psum[0] += __shfl_xor_sync(0xffffffffu, psum[0], off);
                psum[1] += __shfl_xor_sync(0xffffffffu, psum[1], off);
            }
            l_i[0] = l_i[0] * corr0 + psum[0];
            l_i[1] = l_i[1] * corr1 + psum[1];

#pragma unroll
            for (int dt = 0; dt < 8; dt++) {
                o[dt][0] *= corr0; o[dt][1] *= corr0;
                o[dt][2] *= corr1; o[dt][3] *= corr1;
            }
            __syncwarp();

            // ---- O += P V (V row-major: B[n][k] = Vs[k][n]) ----
#pragma unroll
            for (int ks = 0; ks < 8; ks++) {
                int k = ks * 8;
                float a[4];
                a[0] = Ps[(m0 + gr) * FSTR + k + gc];
                a[1] = Ps[(m0 + gr + 8) * FSTR + k + gc];
                a[2] = Ps[(m0 + gr) * FSTR + k + gc + 4];
                a[3] = Ps[(m0 + gr + 8) * FSTR + k + gc + 4];
#pragma unroll
                for (int nt = 0; nt < 8; nt++) {
                    float b[2];
                    b[0] = Vs[(k + gc) * VSTR + nt * 8 + gr];
                    b[1] = Vs[(k + gc + 4) * VSTR + nt * 8 + gr];
                    mma_tf32(o[nt], a, b);
                }
            }
            __syncwarp();
        }

        float linv0 = 1.f / l_i[0], linv1 = 1.f / l_i[1];
        int r0g = q0 + m0 + gr;
        float* ob0 = g_ysharp + ((size_t)bh * Tv + r0g) * Dv;
        float* ob1 = g_ysharp + ((size_t)bh * Tv + r0g + 8) * Dv;
#pragma unroll
        for (int dt = 0; dt < 8; dt++) {
            int cb = dt * 8 + 2 * gc;
            ob0[cb]     = o[dt][0] * linv0;
            ob0[cb + 1] = o[dt][1] * linv0;
            ob1[cb]     = o[dt][2] * linv1;
            ob1[cb + 1] = o[dt][3] * linv1;
        }
    }
}

// ========== K3: linear attention phase A (per-chunk, TF32 mma) ==========
#define LSTR 68
__global__ void __launch_bounds__(256, 2) lin_a_kernel() {
    extern __shared__ float sm[];
    float* Qp  = sm;                 // [64][LSTR] t-major
    float* Kp  = Qp  + 64 * LSTR;    // [64][LSTR] t-major
    float* KpT = Kp  + 64 * LSTR;    // [64][LSTR] d-major
    float* Vt  = KpT + 64 * LSTR;    // [64][LSTR] e-major
    float* As  = Vt  + 64 * LSTR;    // [64][LSTR] masked S

    int bh = blockIdx.y, ch = blockIdx.x;
    int tid = threadIdx.x, lane = tid & 31, wid = tid >> 5;
    int gr = lane >> 2, gc = lane & 3;
    int m0 = (wid >> 1) * 16, n0 = (wid & 1) * 32;

    const float* qb = g_qkv + ((size_t)bh * Tv + ch * 64) * Dv;
    const float* kb = qb + QSZ;
    const float* vb = qb + 2 * QSZ;
    for (int i = tid; i < 1024; i += 256) {
        int t = i >> 4, c4 = (i & 15) * 4;
        float4 f = *(const float4*)&qb[t * 64 + c4];
        Qp[t * LSTR + c4 + 0] = elu1(f.x * 0.125f);
        Qp[t * LSTR + c4 + 1] = elu1(f.y * 0.125f);
        Qp[t * LSTR + c4 + 2] = elu1(f.z * 0.125f);
        Qp[t * LSTR + c4 + 3] = elu1(f.w * 0.125f);
        float4 g = *(const float4*)&kb[t * 64 + c4];
        float k0 = elu1(g.x * 0.125f), k1 = elu1(g.y * 0.125f);
        float k2 = elu1(g.z * 0.125f), k3 = elu1(g.w * 0.125f);
        Kp[t * LSTR + c4 + 0] = k0; Kp[t * LSTR + c4 + 1] = k1;
        Kp[t * LSTR + c4 + 2] = k2; Kp[t * LSTR + c4 + 3] = k3;
        KpT[(c4 + 0) * LSTR + t] = k0; KpT[(c4 + 1) * LSTR + t] = k1;
        KpT[(c4 + 2) * LSTR + t] = k2; KpT[(c4 + 3) * LSTR + t] = k3;
        float4 h = *(const float4*)&vb[t * 64 + c4];
        Vt[(c4 + 0) * LSTR + t] = h.x; Vt[(c4 + 1) * LSTR + t] = h.y;
        Vt[(c4 + 2) * LSTR + t] = h.z; Vt[(c4 + 3) * LSTR + t] = h.w;
    }
    __syncthreads();

    float s[4][4];
#pragma unroll
    for (int nt = 0; nt < 4; nt++)
#pragma unroll
        for (int r = 0; r < 4; r++) s[nt][r] = 0.f;
#pragma unroll
    for (int ks = 0; ks < 8; ks++) {
        int k = ks * 8;
        float a[4];
        a[0] = Qp[(m0 + gr) * LSTR + k + gc];
        a[1] = Qp[(m0 + gr + 8) * LSTR + k + gc];
        a[2] = Qp[(m0 + gr) * LSTR + k + gc + 4];
        a[3] = Qp[(m0 + gr + 8) * LSTR + k + gc + 4];
#pragma unroll
        for (int nt = 0; nt < 4; nt++) {
            float b[2];
            b[0] = Kp[(n0 + nt * 8 + gr) * LSTR + k + gc];
            b[1] = Kp[(n0 + nt * 8 + gr) * LSTR + k + gc + 4];
            mma_tf32(s[nt], a, b);
        }
    }
    {
        int r0 = m0 + gr;
#pragma unroll
        for (int nt = 0; nt < 4; nt++) {
            int c0 = n0 + nt * 8 + 2 * gc;
            As[r0 * LSTR + c0]           = (c0     <= r0)     ? s[nt][0] : 0.f;
            As[r0 * LSTR + c0 + 1]       = (c0 + 1 <= r0)     ? s[nt][1] : 0.f;
            As[(r0 + 8) * LSTR + c0]     = (c0     <= r0 + 8) ? s[nt][2] : 0.f;
            As[(r0 + 8) * LSTR + c0 + 1] = (c0 + 1 <= r0 + 8) ? s[nt][3] : 0.f;
        }
    }
    __syncthreads();

    if (tid < 64) {
        float ds = 0.f, kss = 0.f;
#pragma unroll
        for (int j = 0; j < 16; j++) {
            float4 fa = *(const float4*)&As[tid * LSTR + j * 4];
            ds += fa.x + fa.y + fa.z + fa.w;
            float4 fk = *(const float4*)&KpT[tid * LSTR + j * 4];
            kss += fk.x + fk.y + fk.z + fk.w;
        }
        g_dintra[(size_t)bh * Tv + ch * 64 + tid] = ds;
        g_ks[((size_t)bh * NCH + ch) * Dv + tid] = kss;
    }

    float y[4][4], st[4][4];
#pragma unroll
    for (int nt = 0; nt < 4; nt++)
#pragma unroll
        for (int r = 0; r < 4; r++) { y[nt][r] = 0.f; st[nt][r] = 0.f; }
#pragma unroll
    for (int ks = 0; ks < 8; ks++) {
        int k = ks * 8;
        float a1[4], a2[4];
        a1[0] = As[(m0 + gr) * LSTR + k + gc];
        a1[1] = As[(m0 + gr + 8) * LSTR + k + gc];
        a1[2] = As[(m0 + gr) * LSTR + k + gc + 4];
        a1[3] = As[(m0 + gr + 8) * LSTR + k + gc + 4];
        a2[0] = KpT[(m0 + gr) * LSTR + k + gc];
        a2[1] = KpT[(m0 + gr + 8) * LSTR + k + gc];
        a2[2] = KpT[(m0 + gr) * LSTR + k + gc + 4];
        a2[3] = KpT[(m0 + gr + 8) * LSTR + k + gc + 4];
#pragma unroll
        for (int nt = 0; nt < 4; nt++) {
            float b[2];
            b[0] = Vt[(n0 + nt * 8 + gr) * LSTR + k + gc];
            b[1] = Vt[(n0 + nt * 8 + gr) * LSTR + k + gc + 4];
            mma_tf32(y[nt], a1, b);
            mma_tf32(st[nt], a2, b);
        }
    }
    float* yb = g_yintra + ((size_t)bh * Tv + ch * 64) * Dv;
    float* sb = g_Sc + ((size_t)bh * NCH + ch) * (Dv * Dv);
    {
        int r0 = m0 + gr;
#pragma unroll
        for (int nt = 0; nt < 4; nt++) {
            int c0 = n0 + nt * 8 + 2 * gc;
            yb[r0 * 64 + c0]           = y[nt][0];
            yb[r0 * 64 + c0 + 1]       = y[nt][1];
            yb[(r0 + 8) * 64 + c0]     = y[nt][2];
            yb[(r0 + 8) * 64 + c0 + 1] = y[nt][3];
            sb[r0 * 64 + c0]           = st[nt][0];
            sb[r0 * 64 + c0 + 1]       = st[nt][1];
            sb[(r0 + 8) * 64 + c0]     = st[nt][2];
            sb[(r0 + 8) * 64 + c0 + 1] = st[nt][3];
        }
    }
}

// ========== K4: linear attention phase B (exclusive prefix over chunks) ==========
// grid (BH, 16): 256 elements per block -> 512 blocks for better DRAM parallelism.
__global__ void lin_b_kernel() {
    int bh = blockIdx.x, tid = threadIdx.x;
    float* sb = g_Sc + (size_t)bh * NCH * Dv * Dv;
    int e = blockIdx.y * 256 + tid;
    {
        float v[NCH];
#pragma unroll
        for (int cc = 0; cc < NCH; cc++) v[cc] = sb[cc * (Dv * Dv) + e];
        float run = 0.f;
#pragma unroll
        for (int cc = 0; cc < NCH; cc++) {
            float t = v[cc];
            sb[cc * (Dv * Dv) + e] = run;
            run += t;
        }
    }
    if (blockIdx.y == 0 && tid < 64) {
        float* kb = g_ks + (size_t)bh * NCH * Dv;
        float v[NCH];
#pragma unroll
        for (int cc = 0; cc < NCH; cc++) v[cc] = kb[cc * Dv + tid];
        float run = 0.f;
#pragma unroll
        for (int cc = 0; cc < NCH; cc++) {
            kb[cc * Dv + tid] = run;
            run += v[cc];
        }
    }
}

// ========== K5: lin_c: numer = Qp*Sp + yintra (mma), den, LN(D), gate-combine ==========
__global__ void __launch_bounds__(256, 2) lin_c_kernel(const float* __restrict__ fgate,
                                                       const float* __restrict__ ang,
                                                       const float* __restrict__ anb) {
    extern __shared__ float sm[];
    float* Qp  = sm;                 // [64][LSTR]
    float* SpT = Qp + 64 * LSTR;     // [64][LSTR]
    float* Nm  = SpT + 64 * LSTR;    // [64][LSTR]
    float* den = Nm + 64 * LSTR;     // [64]
    float* kp  = den + 64;           // [64]
    float* gsh = kp + 64;            // [64]
    float* bsh = gsh + 64;           // [64]

    int bh = blockIdx.y, ch = blockIdx.x;
    int b = bh >> 4, h = bh & 15;
    int tid = threadIdx.x, lane = tid & 31, wid = tid >> 5;
    int gr = lane >> 2, gc = lane & 3;
    int m0 = (wid >> 1) * 16, n0 = (wid & 1) * 32;

    const float* qb = g_qkv + ((size_t)bh * Tv + ch * 64) * Dv;
    const float* spg = g_Sc + ((size_t)bh * NCH + ch) * (Dv * Dv);
    const float* yig = g_yintra + ((size_t)bh * Tv + ch * 64) * Dv;
    for (int i = tid; i < 1024; i += 256) {
        int r = i >> 4, c4 = (i & 15) * 4;
        float4 f = *(const float4*)&qb[r * 64 + c4];
        Qp[r * LSTR + c4 + 0] = elu1(f.x * 0.125f);
        Qp[r * LSTR + c4 + 1] = elu1(f.y * 0.125f);
        Qp[r * LSTR + c4 + 2] = elu1(f.z * 0.125f);
        Qp[r * LSTR + c4 + 3] = elu1(f.w * 0.125f);
        float4 g = *(const float4*)&spg[r * 64 + c4];
        SpT[(c4 + 0) * LSTR + r] = g.x; SpT[(c4 + 1) * LSTR + r] = g.y;
        SpT[(c4 + 2) * LSTR + r] = g.z; SpT[(c4 + 3) * LSTR + r] = g.w;
        float4 yv = *(const float4*)&yig[r * 64 + c4];
        *(float4*)&Nm[r * LSTR + c4] = yv;
    }
    if (tid < 64) {
        kp[tid]  = g_ks[((size_t)bh * NCH + ch) * Dv + tid];
        gsh[tid] = ang[tid];
        bsh[tid] = anb[tid];
    }
    __syncthreads();

    if (tid < 64) {
        float ds = g_dintra[(size_t)bh * Tv + ch * 64 + tid];
#pragma unroll
        for (int j = 0; j < 16; j++) {
            float4 q4 = *(const float4*)&Qp[tid * LSTR + j * 4];
            ds += q4.x * kp[j * 4] + q4.y * kp[j * 4 + 1]
                + q4.z * kp[j * 4 + 2] + q4.w * kp[j * 4 + 3];
        }
        den[tid] = ds + 1e-4f;
    }

    float c[4][4];
#pragma unroll
    for (int nt = 0; nt < 4; nt++)
#pragma unroll
        for (int r = 0; r < 4; r++) c[nt][r] = 0.f;
#pragma unroll
    for (int ks = 0; ks < 8; ks++) {
        int k = ks * 8;
        float a[4];
        a[0] = Qp[(m0 + gr) * LSTR + k + gc];
        a[1] = Qp[(m0 + gr + 8) * LSTR + k + gc];
        a[2] = Qp[(m0 + gr) * LSTR + k + gc + 4];
        a[3] = Qp[(m0 + gr + 8) * LSTR + k + gc + 4];
#pragma unroll
        for (int nt = 0; nt < 4; nt++) {
            float bb[2];
            bb[0] = SpT[(n0 + nt * 8 + gr) * LSTR + k + gc];
            bb[1] = SpT[(n0 + nt * 8 + gr) * LSTR + k + gc + 4];
            mma_tf32(c[nt], a, bb);
        }
    }
    __syncthreads();
    {
        int r0 = m0 + gr;
#pragma unroll
        for (int nt = 0; nt < 4; nt++) {
            int c0 = n0 + nt * 8 + 2 * gc;
            Nm[r0 * LSTR + c0]           += c[nt][0];
            Nm[r0 * LSTR + c0 + 1]       += c[nt][1];
            Nm[(r0 + 8) * LSTR + c0]     += c[nt][2];
            Nm[(r0 + 8) * LSTR + c0 + 1] += c[nt][3];
        }
    }
    __syncthreads();

    float al = 1.f / (1.f + __expf(-fgate[0]));
    const float* ysb = g_ysharp + ((size_t)bh * Tv + ch * 64) * Dv;
    float* yob = g_y + ((size_t)(b * Tv + ch * 64)) * Cv + h * 64;
#pragma unroll
    for (int rr = 0; rr < 8; rr++) {
        int t = wid * 8 + rr;
        float dinv = 1.f / den[t];
        float yl0 = Nm[t * LSTR + lane] * dinv;
        float yl1 = Nm[t * LSTR + lane + 32] * dinv;
        float s1 = yl0 + yl1, s2 = yl0 * yl0 + yl1 * yl1;
#pragma unroll
        for (int off = 16; off; off >>= 1) {
            s1 += __shfl_xor_sync(0xffffffffu, s1, off);
            s2 += __shfl_xor_sync(0xffffffffu, s2, off);
        }
        float mean = s1 * (1.f / 64.f);
        float var = s2 * (1.f / 64.f) - mean * mean;
        float inv = rsqrtf(var + 1e-5f);
        float yln0 = (yl0 - mean) * inv * gsh[lane] + bsh[lane];
        float yln1 = (yl1 - mean) * inv * gsh[lane + 32] + bsh[lane + 32];
        float ys0 = ysb[t * 64 + lane];
        float ys1 = ysb[t * 64 + lane + 32];
        yob[(size_t)t * Cv + lane]      = al * ys0 + (1.f - al) * yln0;
        yob[(size_t)t * Cv + lane + 32] = al * ys1 + (1.f - al) * yln1;
    }
}

// =================== K6: fused double-LN + HBS projection ===================
__device__ __forceinline__ float blockReduceSum(float v, float* red) {
    for (int o = 16; o; o >>= 1) v += __shfl_xor_sync(0xffffffffu, v, o);
    __syncthreads();
    if ((threadIdx.x & 31) == 0) red[threadIdx.x >> 5] = v;
    __syncthreads();
    float t = red[0];
#pragma unroll
    for (int i = 1; i < 8; i++) t += red[i];
    return t;
}

__global__ void post_kernel(const float* __restrict__ og, const float* __restrict__ ob,
                            const float* __restrict__ pg, const float* __restrict__ pb,
                            const float* __restrict__ Wb,
                            const float* __restrict__ Wrow,
                            const float* __restrict__ Wcol,
                            const float* __restrict__ palpha,
                            const float* __restrict__ bias,
                            float* __restrict__ out) {
    __shared__ float xr[1024], ym[1024], Zs[1024], Wc[1024], Wr[1024];
    __shared__ float red[8];
    int n = blockIdx.x, tid = threadIdx.x;

    float v[4];
    float s = 0.f, sq = 0.f;
#pragma unroll
    for (int i = 0; i < 4; i++) {
        int c = tid + i * 256;
        float x = g_y[(size_t)n * 1024 + c];
        v[i] = x; s += x; sq += x * x;
        Wc[c] = Wcol[c];
        Wr[c] = Wrow[c];
    }
    s = blockReduceSum(s, red);
    sq = blockReduceSum(sq, red);
    float mean = s * (1.f / 1024.f);
    float inv = rsqrtf(sq * (1.f / 1024.f) - mean * mean + 1e-5f);
    s = 0.f; sq = 0.f;
#pragma unroll
    for (int i = 0; i < 4; i++) {
        int c = tid + i * 256;
        float yn = (v[i] - mean) * inv * og[c] + ob[c];
        v[i] = yn; s += yn; sq += yn * yn;
    }
    s = blockReduceSum(s, red);
    sq = blockReduceSum(sq, red);
    float mean2 = s * (1.f / 1024.f);
    float inv2 = rsqrtf(sq * (1.f / 1024.f) - mean2 * mean2 + 1e-5f);
#pragma unroll
    for (int i = 0; i < 4; i++) {
        int c = tid + i * 256;
        xr[c] = (v[i] - mean2) * inv2 * pg[c] + pb[c];
    }
    __syncthreads();

#pragma unroll
    for (int i = 0; i < 4; i++) {
        int o = tid + i * 256;
        int g = o >> 4, j = o & 15;
        const float* wp = Wb + g * 256 + j;
        float acc = 0.f;
#pragma unroll
        for (int ii = 0; ii < 16; ii++) acc += xr[g * 16 + ii] * wp[ii * 16];
        ym[o] = acc;
    }
#pragma unroll
    for (int i = 0; i < 4; i++) {
        int o = tid + i * 256;
        int r = o >> 5, cc = o & 31;
        float acc = 0.f;
#pragma unroll
        for (int j = 0; j < 32; j++) acc += xr[r * 32 + j] * Wc[j * 32 + cc];
        Zs[o] = acc;
    }
    __syncthreads();
    float pa = palpha[0];
#pragma unroll
    for (int i = 0; i < 4; i++) {
        int c = tid + i * 256;
        int gi = c >> 5, rr = c & 31;
        float z2 = 0.f;
#pragma unroll
        for (int cc = 0; cc < 32; cc++) z2 += Zs[gi * 32 + cc] * Wr[rr * 32 + cc];
        out[(size_t)n * 1024 + c] = ym[1023 - c] + pa * z2 + bias[c];
    }
}

// =================== launch ===================
extern "C" void kernel_launch(void* const* d_in, const int* in_sizes, int n_in,
                              void* d_out, int out_size) {
    const float* x     = (const float*)d_in[0];
    const float* w     = (const float*)d_in[1];
    const float* cb    = (const float*)d_in[2];
    const float* fg    = (const float*)d_in[3];
    const float* ang   = (const float*)d_in[4];
    const float* anb   = (const float*)d_in[5];
    const float* og    = (const float*)d_in[6];
    const float* ob    = (const float*)d_in[7];
    const float* pg    = (const float*)d_in[8];
    const float* pb    = (const float*)d_in[9];
    const float* wb    = (const float*)d_in[10];
    const float* wrow  = (const float*)d_in[11];
    const float* wcol  = (const float*)d_in[12];
    const float* pal   = (const float*)d_in[13];
    const float* pbias = (const float*)d_in[14];
    float* out = (float*)d_out;

    const int FLASH_SMEM = (5 * 64 * FSTR + 64 * VSTR) * 4;   // 105472
    const int LINA_SMEM  = 5 * 64 * LSTR * 4;                 // 87040
    const int LINC_SMEM  = 3 * 64 * LSTR * 4 + 4 * 64 * 4;    // 53248
    cudaFuncSetAttribute(flash_kernel, cudaFuncAttributeMaxDynamicSharedMemorySize, FLASH_SMEM);
    cudaFuncSetAttribute(lin_a_kernel, cudaFuncAttributeMaxDynamicSharedMemorySize, LINA_SMEM);
    cudaFuncSetAttribute(lin_c_kernel, cudaFuncAttributeMaxDynamicSharedMemorySize, LINC_SMEM);

    dim3 g1(24, 16);   // N/128, M/128
    qkv_gemm_kernel<<<g1, 256>>>(x, w, cb);

    dim3 gf(8, 32);    // q-tile pairs, BH
    flash_kernel<<<gf, 128, FLASH_SMEM>>>();

    dim3 g2(16, 32);
    lin_a_kernel<<<g2, 256, LINA_SMEM>>>();
    lin_b_kernel<<<dim3(32, 16), 256>>>();
    lin_c_kernel<<<g2, 256, LINC_SMEM>>>(fg, ang, anb);

    post_kernel<<<Bv * Tv, 256>>>(og, ob, pg, pb, wb, wrow, wcol, pal, pbias, out);
}

// round 16
// speedup vs baseline: 1.4546x; 1.4546x over previous
#include <cuda_runtime.h>
#include <cstdint>
#include <math.h>

#define Bv 2
#define Tv 1024
#define Cv 1024
#define Hv 16
#define Dv 64
#define BHv 32
#define NCH 16          // 16 chunks of 64 tokens
#define QSZ (BHv*Tv*Dv) // 2,097,152

// ---------------- scratch (no allocations allowed) ----------------
__device__ float g_qkv[3u*BHv*Tv*Dv];      // [3][BH][T][D]
__device__ float g_ysharp[BHv*Tv*Dv];      // [BH][T][D]
__device__ float g_yintra[BHv*Tv*Dv];      // [BH][T][D]
__device__ float g_dintra[BHv*Tv];         // [BH][T]
__device__ float g_Sc[BHv*NCH*Dv*Dv];      // chunk states -> exclusive prefix (in place)
__device__ float g_ks[BHv*NCH*Dv];         // chunk ksum   -> exclusive prefix (in place)
__device__ float g_y[Bv*Tv*Cv];            // combined attention output [B,T,C]

__device__ __forceinline__ float elu1(float x) {        // elu(x)+1
    return x > 0.f ? x + 1.f : __expf(x);
}

// ---------------- mma / cp.async helpers ----------------
__device__ __forceinline__ void cpa16(uint32_t s, const void* g) {
    asm volatile("cp.async.cg.shared.global [%0], [%1], 16;\n" :: "r"(s), "l"(g));
}
__device__ __forceinline__ void cpa_commit() {
    asm volatile("cp.async.commit_group;\n");
}
template <int N>
__device__ __forceinline__ void cpa_wait() {
    asm volatile("cp.async.wait_group %0;\n" :: "n"(N));
}
__device__ __forceinline__ void mma_tf32(float* c, const float* a, const float* b) {
    asm volatile(
        "mma.sync.aligned.m16n8k8.row.col.f32.tf32.tf32.f32 "
        "{%0,%1,%2,%3}, {%4,%5,%6,%7}, {%8,%9}, {%0,%1,%2,%3};\n"
        : "+f"(c[0]), "+f"(c[1]), "+f"(c[2]), "+f"(c[3])
        : "r"(__float_as_uint(a[0])), "r"(__float_as_uint(a[1])),
          "r"(__float_as_uint(a[2])), "r"(__float_as_uint(a[3])),
          "r"(__float_as_uint(b[0])), "r"(__float_as_uint(b[1])));
}
__device__ __forceinline__ float tf32_rna(float x) {
    float r;
    asm("cvt.rna.tf32.f32 %0, %1;\n" : "=f"(r) : "f"(x));
    return r;
}

// =================== K1: QKV GEMM (TF32 tensor cores) ===================
#define GSTR 20
__global__ void __launch_bounds__(256, 2) qkv_gemm_kernel(const float* __restrict__ X,
                                                          const float* __restrict__ W,
                                                          const float* __restrict__ bias) {
    __shared__ float As[2][128][GSTR];
    __shared__ float Bs[2][128][GSTR];

    int tid = threadIdx.x;
    int lane = tid & 31, wid = tid >> 5;
    int wm = (wid >> 2) * 64;
    int wn = (wid & 3) * 32;
    int bm = blockIdx.y * 128, bn = blockIdx.x * 128;

    const float* Xb = X + (size_t)bm * 1024;
    const float* Wb = W + (size_t)bn * 1024;

    int lrow = tid >> 2;
    int lc4  = (tid & 3) * 4;

    float c[4][4][4];
#pragma unroll
    for (int mt = 0; mt < 4; mt++)
#pragma unroll
        for (int nt = 0; nt < 4; nt++)
#pragma unroll
            for (int r = 0; r < 4; r++) c[mt][nt][r] = 0.f;

    auto issue = [&](int st, int k0) {
#pragma unroll
        for (int i = 0; i < 2; i++) {
            int row = lrow + i * 64;
            uint32_t sa = (uint32_t)__cvta_generic_to_shared(&As[st][row][lc4]);
            cpa16(sa, &Xb[(size_t)row * 1024 + k0 + lc4]);
            uint32_t sb = (uint32_t)__cvta_generic_to_shared(&Bs[st][row][lc4]);
            cpa16(sb, &Wb[(size_t)row * 1024 + k0 + lc4]);
        }
    };

    const int NK = 64;
    issue(0, 0);
    cpa_commit();

    int lr4 = lane >> 2;
    int lk  = lane & 3;

    for (int kt = 0; kt < NK; kt++) {
        int s = kt & 1;
        if (kt + 1 < NK) { issue(s ^ 1, (kt + 1) * 16); cpa_commit(); cpa_wait<1>(); }
        else             { cpa_wait<0>(); }
        __syncthreads();

#pragma unroll
        for (int ks = 0; ks < 2; ks++) {
            int k8 = ks * 8;
            float a[4][4], b[4][2];
#pragma unroll
            for (int mt = 0; mt < 4; mt++) {
                int r = wm + mt * 16 + lr4;
                a[mt][0] = As[s][r][k8 + lk];
                a[mt][1] = As[s][r + 8][k8 + lk];
                a[mt][2] = As[s][r][k8 + lk + 4];
                a[mt][3] = As[s][r + 8][k8 + lk + 4];
            }
#pragma unroll
            for (int nt = 0; nt < 4; nt++) {
                int n = wn + nt * 8 + lr4;
                b[nt][0] = Bs[s][n][k8 + lk];
                b[nt][1] = Bs[s][n][k8 + lk + 4];
            }
#pragma unroll
            for (int mt = 0; mt < 4; mt++)
#pragma unroll
                for (int nt = 0; nt < 4; nt++)
                    mma_tf32(c[mt][nt], a[mt], b[nt]);
        }
        __syncthreads();
    }

#pragma unroll
    for (int nt = 0; nt < 4; nt++) {
        int n0 = bn + wn + nt * 8 + lk * 2;
#pragma unroll
        for (int jj = 0; jj < 2; jj++) {
            int n = n0 + jj;
            float bb = __ldg(&bias[n]);
            int part = n >> 10, rem = n & 1023, h = rem >> 6, d = rem & 63;
            size_t cbase = (size_t)part * QSZ + (size_t)h * Tv * Dv + d;
#pragma unroll
            for (int mt = 0; mt < 4; mt++) {
                int m0 = bm + wm + mt * 16 + lr4;
#pragma unroll
                for (int ii = 0; ii < 2; ii++) {
                    int m = m0 + ii * 8;
                    int bi = m >> 10, t = m & 1023;
                    g_qkv[cbase + ((size_t)bi * Hv * Tv + t) * Dv] =
                        c[mt][nt][ii * 2 + jj] + bb;
                }
            }
        }
    }
}

// =================== K2: flash softmax attention (causal, TF32 mma) ===================
// grid (8, BH): block pi handles q-tiles (pi, 15-pi) -> 17 k-tiles each.
// 128 threads = 4 warps. Q and K both pre-split hi/lo -> pure LDS+MMA mainloop.
#define FSTR 68
__global__ void __launch_bounds__(128, 2) flash_kernel() {
    extern __shared__ float sm[];
    float* Qhi = sm;                 // [64][FSTR]
    float* Qlo = Qhi + 64 * FSTR;    // [64][FSTR]
    float* Khi = Qlo + 64 * FSTR;    // [64][FSTR]
    float* Klo = Khi + 64 * FSTR;    // [64][FSTR]
    float* Vt  = Klo + 64 * FSTR;    // [64][FSTR] Vt[d][t]
    float* Ps  = Vt  + 64 * FSTR;    // [64][FSTR]

    int bh = blockIdx.y;
    int pi = blockIdx.x;
    int tid = threadIdx.x, lane = tid & 31, wid = tid >> 5;
    int gr = lane >> 2, gc = lane & 3;
    int m0 = wid * 16;

#pragma unroll 1
    for (int pass = 0; pass < 2; pass++) {
        int qt = pass == 0 ? pi : 15 - pi;
        int q0 = qt * 64;

        __syncthreads();
        const float* qb = g_qkv + ((size_t)bh * Tv + q0) * Dv;
        for (int i = tid; i < 1024; i += 128) {
            int row = i >> 4, c4 = (i & 15) * 4;
            float4 f = *(const float4*)&qb[row * 64 + c4];
            float q0v = f.x * 0.125f, q1v = f.y * 0.125f;
            float q2v = f.z * 0.125f, q3v = f.w * 0.125f;
            float h0 = tf32_rna(q0v), h1 = tf32_rna(q1v);
            float h2 = tf32_rna(q2v), h3 = tf32_rna(q3v);
            float* dh = &Qhi[row * FSTR + c4];
            dh[0] = h0; dh[1] = h1; dh[2] = h2; dh[3] = h3;
            float* dl = &Qlo[row * FSTR + c4];
            dl[0] = q0v - h0; dl[1] = q1v - h1;
            dl[2] = q2v - h2; dl[3] = q3v - h3;
        }

        float m_i[2] = {-1e30f, -1e30f};
        float l_i[2] = {0.f, 0.f};
        float o[8][4];
#pragma unroll
        for (int dt = 0; dt < 8; dt++)
#pragma unroll
            for (int r = 0; r < 4; r++) o[dt][r] = 0.f;

#pragma unroll 1
        for (int kt = 0; kt <= qt; kt++) {
            const float* kb = g_qkv + QSZ + ((size_t)bh * Tv + kt * 64) * Dv;
            const float* vb = kb + QSZ;
            __syncthreads();
            for (int i = tid; i < 1024; i += 128) {
                int row = i >> 4, c4 = (i & 15) * 4;
                float4 f = *(const float4*)&kb[row * 64 + c4];
                float h0 = tf32_rna(f.x), h1 = tf32_rna(f.y);
                float h2 = tf32_rna(f.z), h3 = tf32_rna(f.w);
                float* dh = &Khi[row * FSTR + c4];
                dh[0] = h0; dh[1] = h1; dh[2] = h2; dh[3] = h3;
                float* dl = &Klo[row * FSTR + c4];
                dl[0] = f.x - h0; dl[1] = f.y - h1;
                dl[2] = f.z - h2; dl[3] = f.w - h3;
                float4 g = *(const float4*)&vb[row * 64 + c4];
                Vt[(c4 + 0) * FSTR + row] = g.x;
                Vt[(c4 + 1) * FSTR + row] = g.y;
                Vt[(c4 + 2) * FSTR + row] = g.z;
                Vt[(c4 + 3) * FSTR + row] = g.w;
            }
            __syncthreads();

            // ---- S = Q K^T (3-term split-tf32; both sides pre-split) ----
            float s[8][4];
#pragma unroll
            for (int nt = 0; nt < 8; nt++)
#pragma unroll
                for (int r = 0; r < 4; r++) s[nt][r] = 0.f;

#pragma unroll
            for (int ks = 0; ks < 8; ks++) {
                int k = ks * 8;
                float ah[4], al[4];
                ah[0] = Qhi[(m0 + gr) * FSTR + k + gc];
                ah[1] = Qhi[(m0 + gr + 8) * FSTR + k + gc];
                ah[2] = Qhi[(m0 + gr) * FSTR + k + gc + 4];
                ah[3] = Qhi[(m0 + gr + 8) * FSTR + k + gc + 4];
                al[0] = Qlo[(m0 + gr) * FSTR + k + gc];
                al[1] = Qlo[(m0 + gr + 8) * FSTR + k + gc];
                al[2] = Qlo[(m0 + gr) * FSTR + k + gc + 4];
                al[3] = Qlo[(m0 + gr + 8) * FSTR + k + gc + 4];
#pragma unroll
                for (int nt = 0; nt < 8; nt++) {
                    float bhv[2], blv[2];
                    bhv[0] = Khi[(nt * 8 + gr) * FSTR + k + gc];
                    bhv[1] = Khi[(nt * 8 + gr) * FSTR + k + gc + 4];
                    blv[0] = Klo[(nt * 8 + gr) * FSTR + k + gc];
                    blv[1] = Klo[(nt * 8 + gr) * FSTR + k + gc + 4];
                    mma_tf32(s[nt], ah, bhv);
                    mma_tf32(s[nt], ah, blv);
                    mma_tf32(s[nt], al, bhv);
                }
            }

            // ---- causal mask (only the diagonal tile is partial) ----
            if (kt == qt) {
                int lr = m0 + gr;
#pragma unroll
                for (int nt = 0; nt < 8; nt++) {
                    int c0 = nt * 8 + 2 * gc;
                    if (c0 > lr)     s[nt][0] = -1e30f;
                    if (c0 + 1 > lr) s[nt][1] = -1e30f;
                    if (c0 > lr + 8)     s[nt][2] = -1e30f;
                    if (c0 + 1 > lr + 8) s[nt][3] = -1e30f;
                }
            }

            // ---- online softmax ----
            float mx[2] = {m_i[0], m_i[1]};
#pragma unroll
            for (int nt = 0; nt < 8; nt++) {
                mx[0] = fmaxf(mx[0], fmaxf(s[nt][0], s[nt][1]));
                mx[1] = fmaxf(mx[1], fmaxf(s[nt][2], s[nt][3]));
            }
#pragma unroll
            for (int off = 1; off <= 2; off <<= 1) {
                mx[0] = fmaxf(mx[0], __shfl_xor_sync(0xffffffffu, mx[0], off));
                mx[1] = fmaxf(mx[1], __shfl_xor_sync(0xffffffffu, mx[1], off));
            }
            float corr0 = __expf(m_i[0] - mx[0]);
            float corr1 = __expf(m_i[1] - mx[1]);
            m_i[0] = mx[0]; m_i[1] = mx[1];

            float psum[2] = {0.f, 0.f};
#pragma unroll
            for (int nt = 0; nt < 8; nt++) {
                float p0 = tf32_rna(__expf(s[nt][0] - mx[0]));
                float p1 = tf32_rna(__expf(s[nt][1] - mx[0]));
                float p2 = tf32_rna(__expf(s[nt][2] - mx[1]));
                float p3 = tf32_rna(__expf(s[nt][3] - mx[1]));
                psum[0] += p0 + p1; psum[1] += p2 + p3;
                int cb = nt * 8 + 2 * gc;
                Ps[(m0 + gr) * FSTR + cb]     = p0;
                Ps[(m0 + gr) * FSTR + cb + 1] = p1;
                Ps[(m0 + gr + 8) * FSTR + cb]     = p2;
                Ps[(m0 + gr + 8) * FSTR + cb + 1] = p3;
            }
#pragma unroll
            for (int off = 1; off <= 2; off <<= 1) {
                psum[0] += __shfl_xor_sync(0xffffffffu, psum[0], off);
                psum[1] += __shfl_xor_sync(0xffffffffu, psum[1], off);
            }
            l_i[0] = l_i[0] * corr0 + psum[0];
            l_i[1] = l_i[1] * corr1 + psum[1];

#pragma unroll
            for (int dt = 0; dt < 8; dt++) {
                o[dt][0] *= corr0; o[dt][1] *= corr0;
                o[dt][2] *= corr1; o[dt][3] *= corr1;
            }
            __syncwarp();

            // ---- O += P V ----
#pragma unroll
            for (int ks = 0; ks < 8; ks++) {
                int k = ks * 8;
                float a[4];
                a[0] = Ps[(m0 + gr) * FSTR + k + gc];
                a[1] = Ps[(m0 + gr + 8) * FSTR + k + gc];
                a[2] = Ps[(m0 + gr) * FSTR + k + gc + 4];
                a[3] = Ps[(m0 + gr + 8) * FSTR + k + gc + 4];
#pragma unroll
                for (int nt = 0; nt < 8; nt++) {
                    float b[2];
                    b[0] = Vt[(nt * 8 + gr) * FSTR + k + gc];
                    b[1] = Vt[(nt * 8 + gr) * FSTR + k + gc + 4];
                    mma_tf32(o[nt], a, b);
                }
            }
            __syncwarp();
        }

        float linv0 = 1.f / l_i[0], linv1 = 1.f / l_i[1];
        int r0g = q0 + m0 + gr;
        float* ob0 = g_ysharp + ((size_t)bh * Tv + r0g) * Dv;
        float* ob1 = g_ysharp + ((size_t)bh * Tv + r0g + 8) * Dv;
#pragma unroll
        for (int dt = 0; dt < 8; dt++) {
            int cb = dt * 8 + 2 * gc;
            ob0[cb]     = o[dt][0] * linv0;
            ob0[cb + 1] = o[dt][1] * linv0;
            ob1[cb]     = o[dt][2] * linv1;
            ob1[cb + 1] = o[dt][3] * linv1;
        }
    }
}

// ========== K3: linear attention phase A (per-chunk, TF32 mma) ==========
#define LSTR 68
__global__ void __launch_bounds__(256, 2) lin_a_kernel() {
    extern __shared__ float sm[];
    float* Qp  = sm;                 // [64][LSTR] t-major
    float* Kp  = Qp  + 64 * LSTR;    // [64][LSTR] t-major
    float* KpT = Kp  + 64 * LSTR;    // [64][LSTR] d-major
    float* Vt  = KpT + 64 * LSTR;    // [64][LSTR] e-major
    float* As  = Vt  + 64 * LSTR;    // [64][LSTR] masked S

    int bh = blockIdx.y, ch = blockIdx.x;
    int tid = threadIdx.x, lane = tid & 31, wid = tid >> 5;
    int gr = lane >> 2, gc = lane & 3;
    int m0 = (wid >> 1) * 16, n0 = (wid & 1) * 32;

    const float* qb = g_qkv + ((size_t)bh * Tv + ch * 64) * Dv;
    const float* kb = qb + QSZ;
    const float* vb = qb + 2 * QSZ;
    for (int i = tid; i < 1024; i += 256) {
        int t = i >> 4, c4 = (i & 15) * 4;
        float4 f = *(const float4*)&qb[t * 64 + c4];
        Qp[t * LSTR + c4 + 0] = elu1(f.x * 0.125f);
        Qp[t * LSTR + c4 + 1] = elu1(f.y * 0.125f);
        Qp[t * LSTR + c4 + 2] = elu1(f.z * 0.125f);
        Qp[t * LSTR + c4 + 3] = elu1(f.w * 0.125f);
        float4 g = *(const float4*)&kb[t * 64 + c4];
        float k0 = elu1(g.x * 0.125f), k1 = elu1(g.y * 0.125f);
        float k2 = elu1(g.z * 0.125f), k3 = elu1(g.w * 0.125f);
        Kp[t * LSTR + c4 + 0] = k0; Kp[t * LSTR + c4 + 1] = k1;
        Kp[t * LSTR + c4 + 2] = k2; Kp[t * LSTR + c4 + 3] = k3;
        KpT[(c4 + 0) * LSTR + t] = k0; KpT[(c4 + 1) * LSTR + t] = k1;
        KpT[(c4 + 2) * LSTR + t] = k2; KpT[(c4 + 3) * LSTR + t] = k3;
        float4 h = *(const float4*)&vb[t * 64 + c4];
        Vt[(c4 + 0) * LSTR + t] = h.x; Vt[(c4 + 1) * LSTR + t] = h.y;
        Vt[(c4 + 2) * LSTR + t] = h.z; Vt[(c4 + 3) * LSTR + t] = h.w;
    }
    __syncthreads();

    float s[4][4];
#pragma unroll
    for (int nt = 0; nt < 4; nt++)
#pragma unroll
        for (int r = 0; r < 4; r++) s[nt][r] = 0.f;
#pragma unroll
    for (int ks = 0; ks < 8; ks++) {
        int k = ks * 8;
        float a[4];
        a[0] = Qp[(m0 + gr) * LSTR + k + gc];
        a[1] = Qp[(m0 + gr + 8) * LSTR + k + gc];
        a[2] = Qp[(m0 + gr) * LSTR + k + gc + 4];
        a[3] = Qp[(m0 + gr + 8) * LSTR + k + gc + 4];
#pragma unroll
        for (int nt = 0; nt < 4; nt++) {
            float b[2];
            b[0] = Kp[(n0 + nt * 8 + gr) * LSTR + k + gc];
            b[1] = Kp[(n0 + nt * 8 + gr) * LSTR + k + gc + 4];
            mma_tf32(s[nt], a, b);
        }
    }
    {
        int r0 = m0 + gr;
#pragma unroll
        for (int nt = 0; nt < 4; nt++) {
            int c0 = n0 + nt * 8 + 2 * gc;
            As[r0 * LSTR + c0]           = (c0     <= r0)     ? s[nt][0] : 0.f;
            As[r0 * LSTR + c0 + 1]       = (c0 + 1 <= r0)     ? s[nt][1] : 0.f;
            As[(r0 + 8) * LSTR + c0]     = (c0     <= r0 + 8) ? s[nt][2] : 0.f;
            As[(r0 + 8) * LSTR + c0 + 1] = (c0 + 1 <= r0 + 8) ? s[nt][3] : 0.f;
        }
    }
    __syncthreads();

    if (tid < 64) {
        float ds = 0.f, kss = 0.f;
#pragma unroll
        for (int j = 0; j < 16; j++) {
            float4 fa = *(const float4*)&As[tid * LSTR + j * 4];
            ds += fa.x + fa.y + fa.z + fa.w;
            float4 fk = *(const float4*)&KpT[tid * LSTR + j * 4];
            kss += fk.x + fk.y + fk.z + fk.w;
        }
        g_dintra[(size_t)bh * Tv + ch * 64 + tid] = ds;
        g_ks[((size_t)bh * NCH + ch) * Dv + tid] = kss;
    }

    float y[4][4], st[4][4];
#pragma unroll
    for (int nt = 0; nt < 4; nt++)
#pragma unroll
        for (int r = 0; r < 4; r++) { y[nt][r] = 0.f; st[nt][r] = 0.f; }
#pragma unroll
    for (int ks = 0; ks < 8; ks++) {
        int k = ks * 8;
        float a1[4], a2[4];
        a1[0] = As[(m0 + gr) * LSTR + k + gc];
        a1[1] = As[(m0 + gr + 8) * LSTR + k + gc];
        a1[2] = As[(m0 + gr) * LSTR + k + gc + 4];
        a1[3] = As[(m0 + gr + 8) * LSTR + k + gc + 4];
        a2[0] = KpT[(m0 + gr) * LSTR + k + gc];
        a2[1] = KpT[(m0 + gr + 8) * LSTR + k + gc];
        a2[2] = KpT[(m0 + gr) * LSTR + k + gc + 4];
        a2[3] = KpT[(m0 + gr + 8) * LSTR + k + gc + 4];
#pragma unroll
        for (int nt = 0; nt < 4; nt++) {
            float b[2];
            b[0] = Vt[(n0 + nt * 8 + gr) * LSTR + k + gc];
            b[1] = Vt[(n0 + nt * 8 + gr) * LSTR + k + gc + 4];
            mma_tf32(y[nt], a1, b);
            mma_tf32(st[nt], a2, b);
        }
    }
    float* yb = g_yintra + ((size_t)bh * Tv + ch * 64) * Dv;
    float* sb = g_Sc + ((size_t)bh * NCH + ch) * (Dv * Dv);
    {
        int r0 = m0 + gr;
#pragma unroll
        for (int nt = 0; nt < 4; nt++) {
            int c0 = n0 + nt * 8 + 2 * gc;
            yb[r0 * 64 + c0]           = y[nt][0];
            yb[r0 * 64 + c0 + 1]       = y[nt][1];
            yb[(r0 + 8) * 64 + c0]     = y[nt][2];
            yb[(r0 + 8) * 64 + c0 + 1] = y[nt][3];
            sb[r0 * 64 + c0]           = st[nt][0];
            sb[r0 * 64 + c0 + 1]       = st[nt][1];
            sb[(r0 + 8) * 64 + c0]     = st[nt][2];
            sb[(r0 + 8) * 64 + c0 + 1] = st[nt][3];
        }
    }
}

// ========== K4: linear attention phase B (exclusive prefix over chunks) ==========
__global__ void lin_b_kernel() {
    int bh = blockIdx.x, tid = threadIdx.x;
    float* sb = g_Sc + (size_t)bh * NCH * Dv * Dv;
    int base = blockIdx.y * 512;
#pragma unroll
    for (int i = 0; i < 2; i++) {
        int e = base + tid + i * 256;
        float v[NCH];
#pragma unroll
        for (int cc = 0; cc < NCH; cc++) v[cc] = sb[cc * (Dv * Dv) + e];
        float run = 0.f;
#pragma unroll
        for (int cc = 0; cc < NCH; cc++) {
            float t = v[cc];
            sb[cc * (Dv * Dv) + e] = run;
            run += t;
        }
    }
    if (blockIdx.y == 0 && tid < 64) {
        float* kb = g_ks + (size_t)bh * NCH * Dv;
        float v[NCH];
#pragma unroll
        for (int cc = 0; cc < NCH; cc++) v[cc] = kb[cc * Dv + tid];
        float run = 0.f;
#pragma unroll
        for (int cc = 0; cc < NCH; cc++) {
            kb[cc * Dv + tid] = run;
            run += v[cc];
        }
    }
}

// ========== K5: lin_c: numer = Qp*Sp + yintra (mma), den, LN(D), gate-combine ==========
__global__ void __launch_bounds__(256, 2) lin_c_kernel(const float* __restrict__ fgate,
                                                       const float* __restrict__ ang,
                                                       const float* __restrict__ anb) {
    extern __shared__ float sm[];
    float* Qp  = sm;                 // [64][LSTR]
    float* SpT = Qp + 64 * LSTR;     // [64][LSTR]
    float* Nm  = SpT + 64 * LSTR;    // [64][LSTR]
    float* den = Nm + 64 * LSTR;     // [64]
    float* kp  = den + 64;           // [64]
    float* gsh = kp + 64;            // [64]
    float* bsh = gsh + 64;           // [64]

    int bh = blockIdx.y, ch = blockIdx.x;
    int b = bh >> 4, h = bh & 15;
    int tid = threadIdx.x, lane = tid & 31, wid = tid >> 5;
    int gr = lane >> 2, gc = lane & 3;
    int m0 = (wid >> 1) * 16, n0 = (wid & 1) * 32;

    const float* qb = g_qkv + ((size_t)bh * Tv + ch * 64) * Dv;
    const float* spg = g_Sc + ((size_t)bh * NCH + ch) * (Dv * Dv);
    const float* yig = g_yintra + ((size_t)bh * Tv + ch * 64) * Dv;
    for (int i = tid; i < 1024; i += 256) {
        int r = i >> 4, c4 = (i & 15) * 4;
        float4 f = *(const float4*)&qb[r * 64 + c4];
        Qp[r * LSTR + c4 + 0] = elu1(f.x * 0.125f);
        Qp[r * LSTR + c4 + 1] = elu1(f.y * 0.125f);
        Qp[r * LSTR + c4 + 2] = elu1(f.z * 0.125f);
        Qp[r * LSTR + c4 + 3] = elu1(f.w * 0.125f);
        float4 g = *(const float4*)&spg[r * 64 + c4];
        SpT[(c4 + 0) * LSTR + r] = g.x; SpT[(c4 + 1) * LSTR + r] = g.y;
        SpT[(c4 + 2) * LSTR + r] = g.z; SpT[(c4 + 3) * LSTR + r] = g.w;
        float4 yv = *(const float4*)&yig[r * 64 + c4];
        *(float4*)&Nm[r * LSTR + c4] = yv;
    }
    if (tid < 64) {
        kp[tid]  = g_ks[((size_t)bh * NCH + ch) * Dv + tid];
        gsh[tid] = ang[tid];
        bsh[tid] = anb[tid];
    }
    __syncthreads();

    if (tid < 64) {
        float ds = g_dintra[(size_t)bh * Tv + ch * 64 + tid];
#pragma unroll
        for (int j = 0; j < 16; j++) {
            float4 q4 = *(const float4*)&Qp[tid * LSTR + j * 4];
            ds += q4.x * kp[j * 4] + q4.y * kp[j * 4 + 1]
                + q4.z * kp[j * 4 + 2] + q4.w * kp[j * 4 + 3];
        }
        den[tid] = ds + 1e-4f;
    }

    float c[4][4];
#pragma unroll
    for (int nt = 0; nt < 4; nt++)
#pragma unroll
        for (int r = 0; r < 4; r++) c[nt][r] = 0.f;
#pragma unroll
    for (int ks = 0; ks < 8; ks++) {
        int k = ks * 8;
        float a[4];
        a[0] = Qp[(m0 + gr) * LSTR + k + gc];
        a[1] = Qp[(m0 + gr + 8) * LSTR + k + gc];
        a[2] = Qp[(m0 + gr) * LSTR + k + gc + 4];
        a[3] = Qp[(m0 + gr + 8) * LSTR + k + gc + 4];
#pragma unroll
        for (int nt = 0; nt < 4; nt++) {
            float bb[2];
            bb[0] = SpT[(n0 + nt * 8 + gr) * LSTR + k + gc];
            bb[1] = SpT[(n0 + nt * 8 + gr) * LSTR + k + gc + 4];
            mma_tf32(c[nt], a, bb);
        }
    }
    __syncthreads();
    {
        int r0 = m0 + gr;
#pragma unroll
        for (int nt = 0; nt < 4; nt++) {
            int c0 = n0 + nt * 8 + 2 * gc;
            Nm[r0 * LSTR + c0]           += c[nt][0];
            Nm[r0 * LSTR + c0 + 1]       += c[nt][1];
            Nm[(r0 + 8) * LSTR + c0]     += c[nt][2];
            Nm[(r0 + 8) * LSTR + c0 + 1] += c[nt][3];
        }
    }
    __syncthreads();

    float al = 1.f / (1.f + __expf(-fgate[0]));
    const float* ysb = g_ysharp + ((size_t)bh * Tv + ch * 64) * Dv;
    float* yob = g_y + ((size_t)(b * Tv + ch * 64)) * Cv + h * 64;
#pragma unroll
    for (int rr = 0; rr < 8; rr++) {
        int t = wid * 8 + rr;
        float dinv = 1.f / den[t];
        float yl0 = Nm[t * LSTR + lane] * dinv;
        float yl1 = Nm[t * LSTR + lane + 32] * dinv;
        float s1 = yl0 + yl1, s2 = yl0 * yl0 + yl1 * yl1;
#pragma unroll
        for (int off = 16; off; off >>= 1) {
            s1 += __shfl_xor_sync(0xffffffffu, s1, off);
            s2 += __shfl_xor_sync(0xffffffffu, s2, off);
        }
        float mean = s1 * (1.f / 64.f);
        float var = s2 * (1.f / 64.f) - mean * mean;
        float inv = rsqrtf(var + 1e-5f);
        float yln0 = (yl0 - mean) * inv * gsh[lane] + bsh[lane];
        float yln1 = (yl1 - mean) * inv * gsh[lane + 32] + bsh[lane + 32];
        float ys0 = ysb[t * 64 + lane];
        float ys1 = ysb[t * 64 + lane + 32];
        yob[(size_t)t * Cv + lane]      = al * ys0 + (1.f - al) * yln0;
        yob[(size_t)t * Cv + lane + 32] = al * ys1 + (1.f - al) * yln1;
    }
}

// =================== K6: fused double-LN + HBS projection ===================
__device__ __forceinline__ float blockReduceSum(float v, float* red) {
    for (int o = 16; o; o >>= 1) v += __shfl_xor_sync(0xffffffffu, v, o);
    __syncthreads();
    if ((threadIdx.x & 31) == 0) red[threadIdx.x >> 5] = v;
    __syncthreads();
    float t = red[0];
#pragma unroll
    for (int i = 1; i < 8; i++) t += red[i];
    return t;
}

__global__ void post_kernel(const float* __restrict__ og, const float* __restrict__ ob,
                            const float* __restrict__ pg, const float* __restrict__ pb,
                            const float* __restrict__ Wb,
                            const float* __restrict__ Wrow,
                            const float* __restrict__ Wcol,
                            const float* __restrict__ palpha,
                            const float* __restrict__ bias,
                            float* __restrict__ out) {
    __shared__ float xr[1024], ym[1024], Zs[1024], Wc[1024], Wr[1024];
    __shared__ float red[8];
    int n = blockIdx.x, tid = threadIdx.x;

    float v[4];
    float s = 0.f, sq = 0.f;
#pragma unroll
    for (int i = 0; i < 4; i++) {
        int c = tid + i * 256;
        float x = g_y[(size_t)n * 1024 + c];
        v[i] = x; s += x; sq += x * x;
        Wc[c] = Wcol[c];
        Wr[c] = Wrow[c];
    }
    s = blockReduceSum(s, red);
    sq = blockReduceSum(sq, red);
    float mean = s * (1.f / 1024.f);
    float inv = rsqrtf(sq * (1.f / 1024.f) - mean * mean + 1e-5f);
    s = 0.f; sq = 0.f;
#pragma unroll
    for (int i = 0; i < 4; i++) {
        int c = tid + i * 256;
        float yn = (v[i] - mean) * inv * og[c] + ob[c];
        v[i] = yn; s += yn; sq += yn * yn;
    }
    s = blockReduceSum(s, red);
    sq = blockReduceSum(sq, red);
    float mean2 = s * (1.f / 1024.f);
    float inv2 = rsqrtf(sq * (1.f / 1024.f) - mean2 * mean2 + 1e-5f);
#pragma unroll
    for (int i = 0; i < 4; i++) {
        int c = tid + i * 256;
        xr[c] = (v[i] - mean2) * inv2 * pg[c] + pb[c];
    }
    __syncthreads();

#pragma unroll
    for (int i = 0; i < 4; i++) {
        int o = tid + i * 256;
        int g = o >> 4, j = o & 15;
        const float* wp = Wb + g * 256 + j;
        float acc = 0.f;
#pragma unroll
        for (int ii = 0; ii < 16; ii++) acc += xr[g * 16 + ii] * wp[ii * 16];
        ym[o] = acc;
    }
#pragma unroll
    for (int i = 0; i < 4; i++) {
        int o = tid + i * 256;
        int r = o >> 5, cc = o & 31;
        float acc = 0.f;
#pragma unroll
        for (int j = 0; j < 32; j++) acc += xr[r * 32 + j] * Wc[j * 32 + cc];
        Zs[o] = acc;
    }
    __syncthreads();
    float pa = palpha[0];
#pragma unroll
    for (int i = 0; i < 4; i++) {
        int c = tid + i * 256;
        int gi = c >> 5, rr = c & 31;
        float z2 = 0.f;
#pragma unroll
        for (int cc = 0; cc < 32; cc++) z2 += Zs[gi * 32 + cc] * Wr[rr * 32 + cc];
        out[(size_t)n * 1024 + c] = ym[1023 - c] + pa * z2 + bias[c];
    }
}

// =================== launch ===================
extern "C" void kernel_launch(void* const* d_in, const int* in_sizes, int n_in,
                              void* d_out, int out_size) {
    const float* x     = (const float*)d_in[0];
    const float* w     = (const float*)d_in[1];
    const float* cb    = (const float*)d_in[2];
    const float* fg    = (const float*)d_in[3];
    const float* ang   = (const float*)d_in[4];
    const float* anb   = (const float*)d_in[5];
    const float* og    = (const float*)d_in[6];
    const float* ob    = (const float*)d_in[7];
    const float* pg    = (const float*)d_in[8];
    const float* pb    = (const float*)d_in[9];
    const float* wb    = (const float*)d_in[10];
    const float* wrow  = (const float*)d_in[11];
    const float* wcol  = (const float*)d_in[12];
    const float* pal   = (const float*)d_in[13];
    const float* pbias = (const float*)d_in[14];
    float* out = (float*)d_out;

    const int FLASH_SMEM = 6 * 64 * FSTR * 4;       // 104448
    const int LINA_SMEM  = 5 * 64 * LSTR * 4;       // 87040
    const int LINC_SMEM  = 3 * 64 * LSTR * 4 + 4 * 64 * 4;  // 53248
    cudaFuncSetAttribute(flash_kernel, cudaFuncAttributeMaxDynamicSharedMemorySize, FLASH_SMEM);
    cudaFuncSetAttribute(lin_a_kernel, cudaFuncAttributeMaxDynamicSharedMemorySize, LINA_SMEM);
    cudaFuncSetAttribute(lin_c_kernel, cudaFuncAttributeMaxDynamicSharedMemorySize, LINC_SMEM);

    dim3 g1(24, 16);   // N/128, M/128
    qkv_gemm_kernel<<<g1, 256>>>(x, w, cb);

    dim3 gf(8, 32);    // q-tile pairs, BH
    flash_kernel<<<gf, 128, FLASH_SMEM>>>();

    dim3 g2(16, 32);
    lin_a_kernel<<<g2, 256, LINA_SMEM>>>();
    lin_b_kernel<<<dim3(32, 8), 256>>>();
    lin_c_kernel<<<g2, 256, LINC_SMEM>>>(fg, ang, anb);

    post_kernel<<<Bv * Tv, 256>>>(og, ob, pg, pb, wb, wrow, wcol, pal, pbias, out);
}